// round 1
// baseline (speedup 1.0000x reference)
#include <cuda_runtime.h>
#include <cuda_bf16.h>

#define P_     2
#define B_     96
#define A_     32
#define N_     (B_*A_)        // 3072
#define MD_    4
#define MA_    4
#define NPOLB_ 8
#define NPOL_  (B_*NPOLB_)    // 768
#define G_     4              // sites per block in pair kernel
#define C_LK_  0.0897935610625833f

struct __align__(16) Site {
    float x, y, z, ri;          // polar atom coord + lj radius
    float cdg, inv_lami;        // cdg = C_LK * dgi * inv_lami * pol_mask
    float w0x, w0y;
    float w0z, w1x, w1y, w1z;   // two water coords (invalid -> 1e4)
    int   b_i;                  // block index of site
    unsigned pdmask;            // bit aj set if path_distance[bti][a_i][aj] >= 4
    int   pad0, pad1;
};                              // 64 bytes

__device__ Site   g_sites[P_*NPOL_];
__device__ float4 g_atom[P_*N_];    // x,y,z, rj
__device__ float  g_voljm[P_*N_];   // volj if heavy else 0
__device__ double g_acc[4];         // [q*2 + p]

// ---------------------------------------------------------------------------
// Prep: per-site waters + coefficients, per-atom packed records, zero accums
// ---------------------------------------------------------------------------
__global__ void __launch_bounds__(256) prep_kernel(
    const float* __restrict__ coords,       // (P,N,3)
    const int*   __restrict__ block_type,   // (P,B)
    const int*   __restrict__ bonds,        // (NT,A,2)
    const int*   __restrict__ ranges,       // (NT,A,2)
    const int*   __restrict__ n_donH,       // (NT)
    const int*   __restrict__ n_acc,        // (NT)
    const int*   __restrict__ donH_inds,    // (NT,MD)
    const int*   __restrict__ don_hvy_inds, // (NT,MD)
    const int*   __restrict__ acc_inds,     // (NT,MA)
    const int*   __restrict__ hybrid,       // (NT,MA)
    const int*   __restrict__ is_h,         // (NT,A)
    const float* __restrict__ lkp,          // (NT,A,4)
    const int*   __restrict__ pdist,        // (NT,A,A)
    const float* __restrict__ wg,           // wdist, wang
    const float* __restrict__ sp2t,
    const float* __restrict__ sp3t,
    const float* __restrict__ ringt)
{
    int t = blockIdx.x * blockDim.x + threadIdx.x;
    if (t < 4) g_acc[t] = 0.0;

    if (t < P_*N_) {
        int p  = t / N_;
        int j  = t - p*N_;
        int bj = j >> 5;        // A_ == 32
        int aj = j & 31;
        int bt = block_type[p*B_ + bj];
        const float* c = coords + (size_t)t*3;
        float rj   = lkp[(bt*A_ + aj)*4 + 0];
        float volj = lkp[(bt*A_ + aj)*4 + 3];
        g_atom[t]  = make_float4(c[0], c[1], c[2], rj);
        g_voljm[t] = (is_h[bt*A_ + aj] != 0) ? 0.f : volj;
    }

    if (t < P_*NPOL_) {
        int p = t / NPOL_;
        int s = t - p*NPOL_;
        int b = s / NPOLB_;
        int k = s - b*NPOLB_;
        int bt = block_type[p*B_ + b];
        const float* cb = coords + (size_t)((p*B_ + b)*A_) * 3;
        float wdist = wg[0], wang = wg[1];
        const float BIG = 1.0e4f;

        int a_i;
        bool mask;
        float w0x, w0y, w0z, w1x, w1y, w1z;

        if (k < MD_) {
            // -------- donor site --------
            mask = (k < n_donH[bt]);
            int hvy_i = don_hvy_inds[bt*MD_ + k];
            int H_i   = donH_inds[bt*MD_ + k];
            float hx = cb[hvy_i*3+0], hy = cb[hvy_i*3+1], hz = cb[hvy_i*3+2];
            float vx = cb[H_i*3+0]-hx, vy = cb[H_i*3+1]-hy, vz = cb[H_i*3+2]-hz;
            float inv = 1.f / sqrtf(vx*vx + vy*vy + vz*vz + 1e-12f);
            w0x = hx + wdist*vx*inv;
            w0y = hy + wdist*vy*inv;
            w0z = hz + wdist*vz*inv;
            w1x = w1y = w1z = BIG;          // donor water slot 1 always invalid
            if (!mask) { w0x = w0y = w0z = BIG; }
            a_i = hvy_i;
        } else {
            // -------- acceptor site --------
            int kk = k - MD_;
            mask = (kk < n_acc[bt]);
            int ai    = acc_inds[bt*MA_ + kk];
            int r1    = ranges[(bt*A_ + ai)*2 + 0];
            int base  = bonds [(bt*A_ + r1)*2 + 1];
            int r2    = ranges[(bt*A_ + base)*2 + 0];
            int base2 = bonds [(bt*A_ + r2)*2 + 1];

            float cx = cb[ai*3+0],    cy = cb[ai*3+1],    cz = cb[ai*3+2];
            float bx = cb[base*3+0],  by = cb[base*3+1],  bz = cb[base*3+2];
            float ax = cb[base2*3+0], ay = cb[base2*3+1], az = cb[base2*3+2];

            // e1 = norm(c - b)
            float e1x = cx-bx, e1y = cy-by, e1z = cz-bz;
            float inv = 1.f / sqrtf(e1x*e1x + e1y*e1y + e1z*e1z + 1e-12f);
            e1x *= inv; e1y *= inv; e1z *= inv;
            // u = b - a;  n = norm(cross(u, e1))
            float ux = bx-ax, uy = by-ay, uz = bz-az;
            float nx = uy*e1z - uz*e1y;
            float ny = uz*e1x - ux*e1z;
            float nz = ux*e1y - uy*e1x;
            inv = 1.f / sqrtf(nx*nx + ny*ny + nz*nz + 1e-12f);
            nx *= inv; ny *= inv; nz *= inv;
            // e2 = cross(n, e1)
            float e2x = ny*e1z - nz*e1y;
            float e2y = nz*e1x - nx*e1z;
            float e2z = nx*e1y - ny*e1x;

            int hyb = hybrid[bt*MA_ + kk];
            const float* tor = (hyb == 0) ? sp2t : (hyb == 1) ? sp3t : ringt;
            float ct = cosf(wang), st = sinf(wang);
            float k1 = -wdist*ct;
            float k2 =  wdist*st;
            float c0 = cosf(tor[0]), s0 = sinf(tor[0]);
            float c1 = cosf(tor[1]), s1 = sinf(tor[1]);
            w0x = cx + k1*e1x + k2*c0*e2x + k2*s0*nx;
            w0y = cy + k1*e1y + k2*c0*e2y + k2*s0*ny;
            w0z = cz + k1*e1z + k2*c0*e2z + k2*s0*nz;
            w1x = cx + k1*e1x + k2*c1*e2x + k2*s1*nx;
            w1y = cy + k1*e1y + k2*c1*e2y + k2*s1*ny;
            w1z = cz + k1*e1z + k2*c1*e2z + k2*s1*nz;
            if (!mask) { w0x=w0y=w0z=BIG; w1x=w1y=w1z=BIG; }
            a_i = ai;
        }

        Site st;
        st.x = cb[a_i*3+0]; st.y = cb[a_i*3+1]; st.z = cb[a_i*3+2];
        float ri   = lkp[(bt*A_ + a_i)*4 + 0];
        float dgi  = lkp[(bt*A_ + a_i)*4 + 1];
        float lami = lkp[(bt*A_ + a_i)*4 + 2];
        float invl = 1.f / lami;
        st.ri = ri;
        st.inv_lami = invl;
        st.cdg = mask ? (C_LK_ * dgi * invl) : 0.f;
        st.w0x = w0x; st.w0y = w0y; st.w0z = w0z;
        st.w1x = w1x; st.w1y = w1y; st.w1z = w1z;
        st.b_i = b;
        const int* pd = pdist + (size_t)(bt*A_ + a_i) * A_;
        unsigned m = 0;
        #pragma unroll
        for (int aj2 = 0; aj2 < A_; aj2++)
            if (pd[aj2] >= 4) m |= (1u << aj2);
        st.pdmask = m;
        st.pad0 = 0; st.pad1 = 0;
        g_sites[t] = st;
    }
}

// ---------------------------------------------------------------------------
// Pair kernel: block = (G_ sites of one pose), threads stride over 3072 atoms.
// Early-out on d2 >= cutoff^2 kills ~95% of pairs before any MUFU work.
// ---------------------------------------------------------------------------
__global__ void __launch_bounds__(256) pair_kernel(
    const int*   __restrict__ msep,   // (P,B,B)
    const float* __restrict__ lkg)    // cutoff, ramp2, d2_low
{
    const int p  = blockIdx.y;
    const int s0 = blockIdx.x * G_;

    __shared__ Site sh[G_];
    {
        const float4* src = (const float4*)&g_sites[p*NPOL_ + s0];
        float4* dst = (float4*)sh;
        for (int i = threadIdx.x; i < G_*4; i += blockDim.x) dst[i] = src[i];
    }
    __syncthreads();

    const float cutoff  = lkg[0];
    const float ramp2   = lkg[1];
    const float d2low   = lkg[2];
    const float cutoff2 = cutoff * cutoff;
    const float thr     = d2low + ramp2;
    const float inv_r2  = 1.f / ramp2;

    float a0 = 0.f, a1 = 0.f;

    for (int j = threadIdx.x; j < N_; j += blockDim.x) {
        float4 cr   = g_atom[p*N_ + j];
        float voljm = g_voljm[p*N_ + j];
        if (voljm == 0.f) continue;               // hydrogen -> no contribution
        int bj = j >> 5;
        int aj = j & 31;

        #pragma unroll
        for (int g = 0; g < G_; g++) {
            const Site& s = sh[g];
            float dx = s.x - cr.x, dy = s.y - cr.y, dz = s.z - cr.z;
            float d2 = fmaxf(dx*dx + dy*dy + dz*dz, 0.01f);
            if (d2 >= cutoff2) continue;          // kills ~95% of pairs

            bool ok = (s.b_i == bj) ? (((s.pdmask >> aj) & 1u) != 0u)
                                    : (msep[(p*B_ + s.b_i)*B_ + bj] >= 4);
            if (!ok) continue;

            float d  = sqrtf(d2);
            float xx = (d - (s.ri + cr.w)) * s.inv_lami;
            float lk = s.cdg * voljm * __expf(-xx*xx) * __frcp_rn(d2);

            float ex = s.w0x - cr.x, ey = s.w0y - cr.y, ez = s.w0z - cr.z;
            float dw0 = ex*ex + ey*ey + ez*ez;
            ex = s.w1x - cr.x; ey = s.w1y - cr.y; ez = s.w1z - cr.z;
            float dw1 = ex*ex + ey*ey + ez*ez;
            float dwmin = fminf(dw0, dw1);

            float wt = fminf(fmaxf((thr - dwmin) * inv_r2, 0.f), 1.f);
            float frac = wt*wt*(3.f - 2.f*wt);

            a0 += lk;
            a1 += lk * frac;
        }
    }

    // block reduction
    #pragma unroll
    for (int off = 16; off > 0; off >>= 1) {
        a0 += __shfl_xor_sync(0xFFFFFFFFu, a0, off);
        a1 += __shfl_xor_sync(0xFFFFFFFFu, a1, off);
    }
    __shared__ float red0[8], red1[8];
    int warp = threadIdx.x >> 5, lane = threadIdx.x & 31;
    if (lane == 0) { red0[warp] = a0; red1[warp] = a1; }
    __syncthreads();
    if (threadIdx.x == 0) {
        float s0 = 0.f, s1 = 0.f;
        #pragma unroll
        for (int w = 0; w < 8; w++) { s0 += red0[w]; s1 += red1[w]; }
        atomicAdd(&g_acc[0 + p], (double)s0);
        atomicAdd(&g_acc[2 + p], (double)s1);
    }
}

__global__ void finalize_kernel(float* __restrict__ out) {
    int t = threadIdx.x;
    if (t < 4) out[t] = (float)g_acc[t];
}

extern "C" void kernel_launch(void* const* d_in, const int* in_sizes, int n_in,
                              void* d_out, int out_size) {
    const float* coords       = (const float*)d_in[0];
    const int*   block_type   = (const int*)  d_in[1];
    const int*   msep         = (const int*)  d_in[2];
    // d_in[3] = bt_n_atoms (unused)
    const int*   bonds        = (const int*)  d_in[4];
    const int*   ranges       = (const int*)  d_in[5];
    const int*   n_donH       = (const int*)  d_in[6];
    const int*   n_acc        = (const int*)  d_in[7];
    const int*   donH_inds    = (const int*)  d_in[8];
    const int*   don_hvy_inds = (const int*)  d_in[9];
    const int*   acc_inds     = (const int*)  d_in[10];
    const int*   hybrid       = (const int*)  d_in[11];
    const int*   is_h         = (const int*)  d_in[12];
    const float* lkp          = (const float*)d_in[13];
    const int*   pdist        = (const int*)  d_in[14];
    const float* lkg          = (const float*)d_in[15];
    const float* wg           = (const float*)d_in[16];
    const float* sp2t         = (const float*)d_in[17];
    const float* sp3t         = (const float*)d_in[18];
    const float* ringt        = (const float*)d_in[19];

    prep_kernel<<<(P_*N_ + 255)/256, 256>>>(
        coords, block_type, bonds, ranges, n_donH, n_acc,
        donH_inds, don_hvy_inds, acc_inds, hybrid, is_h,
        lkp, pdist, wg, sp2t, sp3t, ringt);

    dim3 grid(NPOL_ / G_, P_);
    pair_kernel<<<grid, 256>>>(msep, lkg);

    finalize_kernel<<<1, 32>>>((float*)d_out);
}

// round 2
// speedup vs baseline: 1.4452x; 1.4452x over previous
#include <cuda_runtime.h>
#include <cuda_bf16.h>

#define P_     2
#define B_     96
#define A_     32
#define N_     (B_*A_)        // 3072
#define MD_    4
#define MA_    4
#define NPOLB_ 8
#define NPOL_  (B_*NPOLB_)    // 768
#define G_     8              // sites per block in pair kernel
#define ZCH_   4              // atom chunks
#define CHUNK_ (N_/ZCH_)      // 768 atoms per chunk
#define C_LK_  0.0897935610625833f

typedef unsigned long long u64;

__device__ __forceinline__ u64 pk2(float lo, float hi) {
    u64 r; asm("mov.b64 %0,{%1,%2};" : "=l"(r) : "f"(lo), "f"(hi)); return r;
}
__device__ __forceinline__ void upk2(float& lo, float& hi, u64 v) {
    asm("mov.b64 {%0,%1},%2;" : "=f"(lo), "=f"(hi) : "l"(v));
}
__device__ __forceinline__ u64 add2(u64 a, u64 b) {
    u64 r; asm("add.rn.f32x2 %0,%1,%2;" : "=l"(r) : "l"(a), "l"(b)); return r;
}
__device__ __forceinline__ u64 mul2(u64 a, u64 b) {
    u64 r; asm("mul.rn.f32x2 %0,%1,%2;" : "=l"(r) : "l"(a), "l"(b)); return r;
}
__device__ __forceinline__ u64 fma2(u64 a, u64 b, u64 c) {
    u64 r; asm("fma.rn.f32x2 %0,%1,%2,%3;" : "=l"(r) : "l"(a), "l"(b), "l"(c)); return r;
}

struct __align__(16) Site {
    float x, y, z, ri;
    float cdg, inv_lami;
    float w0x, w0y;
    float w0z, w1x, w1y, w1z;
    int   b_i;
    unsigned pdmask;
    int   pad0, pad1;
};                              // 64 bytes

__device__ Site       g_sites[P_*NPOL_];
__device__ ulonglong2 g_axy[P_*N_];   // {(-x,-x),(-y,-y)} packed
__device__ u64        g_az [P_*N_];   // (-z,-z)
__device__ float2     g_rv [P_*N_];   // rj, voljm (0 if hydrogen)
__device__ double     g_acc[4];
__device__ int        g_done;

// ---------------------------------------------------------------------------
// Prep: blocks [0,24): atoms. blocks [24,216): warp-per-site.
// ---------------------------------------------------------------------------
#define ATOM_BLKS_ 24
__global__ void __launch_bounds__(256) prep_kernel(
    const float* __restrict__ coords,
    const int*   __restrict__ block_type,
    const int*   __restrict__ bonds,
    const int*   __restrict__ ranges,
    const int*   __restrict__ n_donH,
    const int*   __restrict__ n_acc,
    const int*   __restrict__ donH_inds,
    const int*   __restrict__ don_hvy_inds,
    const int*   __restrict__ acc_inds,
    const int*   __restrict__ hybrid,
    const int*   __restrict__ is_h,
    const float* __restrict__ lkp,
    const int*   __restrict__ pdist,
    const float* __restrict__ wg,
    const float* __restrict__ sp2t,
    const float* __restrict__ sp3t,
    const float* __restrict__ ringt)
{
    if (blockIdx.x < ATOM_BLKS_) {
        int t = blockIdx.x * 256 + threadIdx.x;
        if (t < 4) g_acc[t] = 0.0;
        if (t == 4) g_done = 0;
        // atoms
        int p  = t / N_;
        int j  = t - p*N_;
        int bj = j >> 5;
        int aj = j & 31;
        int bt = block_type[p*B_ + bj];
        const float* c = coords + (size_t)t*3;
        float x = c[0], y = c[1], z = c[2];
        float rj   = lkp[(bt*A_ + aj)*4 + 0];
        float volj = lkp[(bt*A_ + aj)*4 + 3];
        ulonglong2 axy; axy.x = pk2(-x, -x); axy.y = pk2(-y, -y);
        g_axy[t] = axy;
        g_az[t]  = pk2(-z, -z);
        g_rv[t]  = make_float2(rj, (is_h[bt*A_ + aj] != 0) ? 0.f : volj);
        return;
    }

    // warp-per-site
    int wgl  = (blockIdx.x - ATOM_BLKS_) * 8 + (threadIdx.x >> 5);
    int lane = threadIdx.x & 31;
    int p = wgl / NPOL_;
    int s = wgl - p*NPOL_;
    int b = s / NPOLB_;
    int k = s - b*NPOLB_;
    int bt = block_type[p*B_ + b];
    const float* cb = coords + (size_t)((p*B_ + b)*A_) * 3;
    float wdist = wg[0], wang = wg[1];
    const float BIG = 1.0e4f;

    int a_i;
    bool mask;
    float w0x, w0y, w0z, w1x, w1y, w1z;

    if (k < MD_) {
        mask = (k < n_donH[bt]);
        int hvy_i = don_hvy_inds[bt*MD_ + k];
        int H_i   = donH_inds[bt*MD_ + k];
        float hx = cb[hvy_i*3+0], hy = cb[hvy_i*3+1], hz = cb[hvy_i*3+2];
        float vx = cb[H_i*3+0]-hx, vy = cb[H_i*3+1]-hy, vz = cb[H_i*3+2]-hz;
        float inv = 1.f / sqrtf(vx*vx + vy*vy + vz*vz + 1e-12f);
        w0x = hx + wdist*vx*inv;
        w0y = hy + wdist*vy*inv;
        w0z = hz + wdist*vz*inv;
        w1x = w1y = w1z = BIG;
        if (!mask) { w0x = w0y = w0z = BIG; }
        a_i = hvy_i;
    } else {
        int kk = k - MD_;
        mask = (kk < n_acc[bt]);
        int ai    = acc_inds[bt*MA_ + kk];
        int r1    = ranges[(bt*A_ + ai)*2 + 0];
        int base  = bonds [(bt*A_ + r1)*2 + 1];
        int r2    = ranges[(bt*A_ + base)*2 + 0];
        int base2 = bonds [(bt*A_ + r2)*2 + 1];

        float cx = cb[ai*3+0],    cy = cb[ai*3+1],    cz = cb[ai*3+2];
        float bx = cb[base*3+0],  by = cb[base*3+1],  bz = cb[base*3+2];
        float ax = cb[base2*3+0], ay = cb[base2*3+1], az = cb[base2*3+2];

        float e1x = cx-bx, e1y = cy-by, e1z = cz-bz;
        float inv = 1.f / sqrtf(e1x*e1x + e1y*e1y + e1z*e1z + 1e-12f);
        e1x *= inv; e1y *= inv; e1z *= inv;
        float ux = bx-ax, uy = by-ay, uz = bz-az;
        float nx = uy*e1z - uz*e1y;
        float ny = uz*e1x - ux*e1z;
        float nz = ux*e1y - uy*e1x;
        inv = 1.f / sqrtf(nx*nx + ny*ny + nz*nz + 1e-12f);
        nx *= inv; ny *= inv; nz *= inv;
        float e2x = ny*e1z - nz*e1y;
        float e2y = nz*e1x - nx*e1z;
        float e2z = nx*e1y - ny*e1x;

        int hyb = hybrid[bt*MA_ + kk];
        const float* tor = (hyb == 0) ? sp2t : (hyb == 1) ? sp3t : ringt;
        float ct = cosf(wang), st = sinf(wang);
        float k1 = -wdist*ct;
        float k2 =  wdist*st;
        float c0 = cosf(tor[0]), s0 = sinf(tor[0]);
        float c1 = cosf(tor[1]), s1 = sinf(tor[1]);
        w0x = cx + k1*e1x + k2*c0*e2x + k2*s0*nx;
        w0y = cy + k1*e1y + k2*c0*e2y + k2*s0*ny;
        w0z = cz + k1*e1z + k2*c0*e2z + k2*s0*nz;
        w1x = cx + k1*e1x + k2*c1*e2x + k2*s1*nx;
        w1y = cy + k1*e1y + k2*c1*e2y + k2*s1*ny;
        w1z = cz + k1*e1z + k2*c1*e2z + k2*s1*nz;
        if (!mask) { w0x=w0y=w0z=BIG; w1x=w1y=w1z=BIG; }
        a_i = ai;
    }

    // warp-parallel path-distance mask
    int pd = pdist[(size_t)(bt*A_ + a_i)*A_ + lane];
    unsigned m = __ballot_sync(0xFFFFFFFFu, pd >= 4);

    if (lane == 0) {
        Site st;
        st.x = cb[a_i*3+0]; st.y = cb[a_i*3+1]; st.z = cb[a_i*3+2];
        float ri   = lkp[(bt*A_ + a_i)*4 + 0];
        float dgi  = lkp[(bt*A_ + a_i)*4 + 1];
        float lami = lkp[(bt*A_ + a_i)*4 + 2];
        float invl = 1.f / lami;
        st.ri = ri;
        st.inv_lami = invl;
        st.cdg = mask ? (C_LK_ * dgi * invl) : 0.f;
        st.w0x = w0x; st.w0y = w0y; st.w0z = w0z;
        st.w1x = w1x; st.w1y = w1y; st.w1z = w1z;
        st.b_i = b;
        st.pdmask = m;
        st.pad0 = 0; st.pad1 = 0;
        g_sites[wgl] = st;
    }
}

// ---------------------------------------------------------------------------
// Pair kernel: grid (96 site-groups, 2 poses, 4 atom chunks), 256 threads.
// Packed f32x2 hot loop: 8 sites per atom at 3 FMA-pipe ops/pair.
// ---------------------------------------------------------------------------
__global__ void __launch_bounds__(256) pair_kernel(
    const int*   __restrict__ msep,
    const float* __restrict__ lkg,
    float*       __restrict__ out)
{
    const int p  = blockIdx.y;
    const int s0 = blockIdx.x * G_;
    const int zb = blockIdx.z * CHUNK_;
    const int tid = threadIdx.x;

    __shared__ Site sh[G_];
    if (tid < G_*4) ((float4*)sh)[tid] = ((const float4*)&g_sites[p*NPOL_ + s0])[tid];
    __syncthreads();

    const float cutoff  = lkg[0];
    const float ramp2   = lkg[1];
    const float d2low   = lkg[2];
    const float c2      = cutoff * cutoff;
    const float inv_r2  = 1.f / ramp2;
    const float thr_s   = (d2low + ramp2) * inv_r2;

    // pack site coords (8 sites -> 4 packed lanes per coord)
    u64 sx2[4], sy2[4], sz2[4];
    #pragma unroll
    for (int h = 0; h < 4; h++) {
        sx2[h] = pk2(sh[2*h].x, sh[2*h+1].x);
        sy2[h] = pk2(sh[2*h].y, sh[2*h+1].y);
        sz2[h] = pk2(sh[2*h].z, sh[2*h+1].z);
    }

    float a0 = 0.f, a1 = 0.f;
    const int base = p*N_ + zb;

    #pragma unroll
    for (int it = 0; it < CHUNK_/256; it++) {
        const int j = it*256 + tid;
        ulonglong2 axy = g_axy[base + j];
        u64        az  = g_az [base + j];
        float2     rv  = g_rv [base + j];
        if (rv.y == 0.f) continue;                 // hydrogen

        float d2s[8];
        #pragma unroll
        for (int h = 0; h < 4; h++) {
            u64 dx = add2(sx2[h], axy.x);
            u64 dy = add2(sy2[h], axy.y);
            u64 dz = add2(sz2[h], az);
            u64 t  = mul2(dx, dx);
            t = fma2(dy, dy, t);
            t = fma2(dz, dz, t);
            upk2(d2s[2*h], d2s[2*h+1], t);
        }

        bool any = (d2s[0]<c2)|(d2s[1]<c2)|(d2s[2]<c2)|(d2s[3]<c2)
                 | (d2s[4]<c2)|(d2s[5]<c2)|(d2s[6]<c2)|(d2s[7]<c2);
        if (!any) continue;

        const int jj = zb + j;
        const int bj = jj >> 5;
        const int aj = jj & 31;
        float nax, nay, naz, dummy;
        upk2(nax, dummy, axy.x);
        upk2(nay, dummy, axy.y);
        upk2(naz, dummy, az);

        #pragma unroll
        for (int g = 0; g < G_; g++) {
            float d2 = d2s[g];
            if (d2 >= c2) continue;
            const Site& s = sh[g];
            bool ok = (s.b_i == bj) ? (((s.pdmask >> aj) & 1u) != 0u)
                                    : (msep[(p*B_ + s.b_i)*B_ + bj] >= 4);
            if (!ok) continue;

            float d2c = fmaxf(d2, 0.01f);
            float d   = sqrtf(d2c);
            float xx  = (d - (s.ri + rv.x)) * s.inv_lami;
            float lk  = s.cdg * rv.y * __expf(-xx*xx) * __frcp_rn(d2c);

            float ex = s.w0x + nax, ey = s.w0y + nay, ez = s.w0z + naz;
            float dw0 = ex*ex + ey*ey + ez*ez;
            ex = s.w1x + nax; ey = s.w1y + nay; ez = s.w1z + naz;
            float dw1 = ex*ex + ey*ey + ez*ez;
            float dwmin = fminf(dw0, dw1);

            float wt = __saturatef(fmaf(dwmin, -inv_r2, thr_s));
            float frac = wt*wt*(3.f - 2.f*wt);

            a0 += lk;
            a1 = fmaf(lk, frac, a1);
        }
    }

    // reduction
    #pragma unroll
    for (int off = 16; off > 0; off >>= 1) {
        a0 += __shfl_xor_sync(0xFFFFFFFFu, a0, off);
        a1 += __shfl_xor_sync(0xFFFFFFFFu, a1, off);
    }
    __shared__ float red0[8], red1[8];
    int warp = tid >> 5, lane = tid & 31;
    if (lane == 0) { red0[warp] = a0; red1[warp] = a1; }
    __syncthreads();
    if (tid == 0) {
        float t0 = 0.f, t1 = 0.f;
        #pragma unroll
        for (int w = 0; w < 8; w++) { t0 += red0[w]; t1 += red1[w]; }
        atomicAdd(&g_acc[0 + p], (double)t0);
        atomicAdd(&g_acc[2 + p], (double)t1);
        __threadfence();
        int done = atomicAdd(&g_done, 1);
        if (done == 96*2*ZCH_ - 1) {
            #pragma unroll
            for (int i = 0; i < 4; i++)
                out[i] = (float)atomicAdd(&g_acc[i], 0.0);
        }
    }
}

extern "C" void kernel_launch(void* const* d_in, const int* in_sizes, int n_in,
                              void* d_out, int out_size) {
    const float* coords       = (const float*)d_in[0];
    const int*   block_type   = (const int*)  d_in[1];
    const int*   msep         = (const int*)  d_in[2];
    const int*   bonds        = (const int*)  d_in[4];
    const int*   ranges       = (const int*)  d_in[5];
    const int*   n_donH       = (const int*)  d_in[6];
    const int*   n_acc        = (const int*)  d_in[7];
    const int*   donH_inds    = (const int*)  d_in[8];
    const int*   don_hvy_inds = (const int*)  d_in[9];
    const int*   acc_inds     = (const int*)  d_in[10];
    const int*   hybrid       = (const int*)  d_in[11];
    const int*   is_h         = (const int*)  d_in[12];
    const float* lkp          = (const float*)d_in[13];
    const int*   pdist        = (const int*)  d_in[14];
    const float* lkg          = (const float*)d_in[15];
    const float* wg           = (const float*)d_in[16];
    const float* sp2t         = (const float*)d_in[17];
    const float* sp3t         = (const float*)d_in[18];
    const float* ringt        = (const float*)d_in[19];

    prep_kernel<<<ATOM_BLKS_ + (P_*NPOL_)/8, 256>>>(
        coords, block_type, bonds, ranges, n_donH, n_acc,
        donH_inds, don_hvy_inds, acc_inds, hybrid, is_h,
        lkp, pdist, wg, sp2t, sp3t, ringt);

    dim3 grid(NPOL_ / G_, P_, ZCH_);
    pair_kernel<<<grid, 256>>>(msep, lkg, (float*)d_out);
}

// round 3
// speedup vs baseline: 1.5302x; 1.0588x over previous
#include <cuda_runtime.h>
#include <cuda_bf16.h>

#define P_     2
#define B_     96
#define A_     32
#define N_     (B_*A_)        // 3072
#define MD_    4
#define MA_    4
#define NPOLB_ 8
#define NPOL_  (B_*NPOLB_)    // 768
#define G_     8              // sites per A-block
#define ZCH_   4              // atom chunks
#define CHUNK_ (N_/ZCH_)      // 768
#define SEG_   16
#define SEGCAP_ 32768
#define NB_B_  256            // phase-B blocks
#define C_LK_  0.0897935610625833f

typedef unsigned long long u64;

__device__ __forceinline__ u64 pk2(float lo, float hi) {
    u64 r; asm("mov.b64 %0,{%1,%2};" : "=l"(r) : "f"(lo), "f"(hi)); return r;
}
__device__ __forceinline__ void upk2(float& lo, float& hi, u64 v) {
    asm("mov.b64 {%0,%1},%2;" : "=f"(lo), "=f"(hi) : "l"(v));
}
__device__ __forceinline__ u64 add2(u64 a, u64 b) {
    u64 r; asm("add.rn.f32x2 %0,%1,%2;" : "=l"(r) : "l"(a), "l"(b)); return r;
}
__device__ __forceinline__ u64 mul2(u64 a, u64 b) {
    u64 r; asm("mul.rn.f32x2 %0,%1,%2;" : "=l"(r) : "l"(a), "l"(b)); return r;
}
__device__ __forceinline__ u64 fma2(u64 a, u64 b, u64 c) {
    u64 r; asm("fma.rn.f32x2 %0,%1,%2,%3;" : "=l"(r) : "l"(a), "l"(b), "l"(c)); return r;
}

struct __align__(16) Site {
    float x, y, z, ri;
    float cdg, inv_lami;
    float w0x, w0y;
    float w0z, w1x, w1y, w1z;
    int   b_i;
    unsigned pdmask;
    int   pad0, pad1;
};                              // 64 bytes

__device__ Site       g_sites[P_*NPOL_];
__device__ ulonglong2 g_axy[P_*N_];    // {(-x,-x),(-y,-y)}
__device__ u64        g_az [P_*N_];    // (-z,-z)
__device__ float2     g_rv [P_*N_];    // rj, voljm (0 if hydrogen)
__device__ float4     g_apos[P_*N_];   // x,y,z,rj
__device__ unsigned   g_cnt[SEG_*32];  // striped counters (128B apart)
__device__ unsigned   g_buf[SEG_*SEGCAP_];
__device__ double     g_acc[4];
__device__ int        g_done;

// ---------------------------------------------------------------------------
// Prep
// ---------------------------------------------------------------------------
#define ATOM_BLKS_ 24
__global__ void __launch_bounds__(256) prep_kernel(
    const float* __restrict__ coords,
    const int*   __restrict__ block_type,
    const int*   __restrict__ bonds,
    const int*   __restrict__ ranges,
    const int*   __restrict__ n_donH,
    const int*   __restrict__ n_acc,
    const int*   __restrict__ donH_inds,
    const int*   __restrict__ don_hvy_inds,
    const int*   __restrict__ acc_inds,
    const int*   __restrict__ hybrid,
    const int*   __restrict__ is_h,
    const float* __restrict__ lkp,
    const int*   __restrict__ pdist,
    const float* __restrict__ wg,
    const float* __restrict__ sp2t,
    const float* __restrict__ sp3t,
    const float* __restrict__ ringt)
{
    if (blockIdx.x < ATOM_BLKS_) {
        int t = blockIdx.x * 256 + threadIdx.x;
        if (t < 4) g_acc[t] = 0.0;
        if (t == 4) g_done = 0;
        if (t >= 8 && t < 8 + SEG_*32) g_cnt[t-8] = 0;
        int p  = t / N_;
        int j  = t - p*N_;
        int bj = j >> 5;
        int aj = j & 31;
        int bt = block_type[p*B_ + bj];
        const float* c = coords + (size_t)t*3;
        float x = c[0], y = c[1], z = c[2];
        float rj   = lkp[(bt*A_ + aj)*4 + 0];
        float volj = lkp[(bt*A_ + aj)*4 + 3];
        ulonglong2 axy; axy.x = pk2(-x, -x); axy.y = pk2(-y, -y);
        g_axy[t] = axy;
        g_az[t]  = pk2(-z, -z);
        g_rv[t]  = make_float2(rj, (is_h[bt*A_ + aj] != 0) ? 0.f : volj);
        g_apos[t] = make_float4(x, y, z, rj);
        return;
    }

    // warp-per-site
    int wgl  = (blockIdx.x - ATOM_BLKS_) * 8 + (threadIdx.x >> 5);
    int lane = threadIdx.x & 31;
    int p = wgl / NPOL_;
    int s = wgl - p*NPOL_;
    int b = s / NPOLB_;
    int k = s - b*NPOLB_;
    int bt = block_type[p*B_ + b];
    const float* cb = coords + (size_t)((p*B_ + b)*A_) * 3;
    float wdist = wg[0], wang = wg[1];
    const float BIG = 1.0e4f;

    int a_i;
    bool mask;
    float w0x, w0y, w0z, w1x, w1y, w1z;

    if (k < MD_) {
        mask = (k < n_donH[bt]);
        int hvy_i = don_hvy_inds[bt*MD_ + k];
        int H_i   = donH_inds[bt*MD_ + k];
        float hx = cb[hvy_i*3+0], hy = cb[hvy_i*3+1], hz = cb[hvy_i*3+2];
        float vx = cb[H_i*3+0]-hx, vy = cb[H_i*3+1]-hy, vz = cb[H_i*3+2]-hz;
        float inv = 1.f / sqrtf(vx*vx + vy*vy + vz*vz + 1e-12f);
        w0x = hx + wdist*vx*inv;
        w0y = hy + wdist*vy*inv;
        w0z = hz + wdist*vz*inv;
        w1x = w1y = w1z = BIG;
        if (!mask) { w0x = w0y = w0z = BIG; }
        a_i = hvy_i;
    } else {
        int kk = k - MD_;
        mask = (kk < n_acc[bt]);
        int ai    = acc_inds[bt*MA_ + kk];
        int r1    = ranges[(bt*A_ + ai)*2 + 0];
        int base  = bonds [(bt*A_ + r1)*2 + 1];
        int r2    = ranges[(bt*A_ + base)*2 + 0];
        int base2 = bonds [(bt*A_ + r2)*2 + 1];

        float cx = cb[ai*3+0],    cy = cb[ai*3+1],    cz = cb[ai*3+2];
        float bx = cb[base*3+0],  by = cb[base*3+1],  bz = cb[base*3+2];
        float ax = cb[base2*3+0], ay = cb[base2*3+1], az = cb[base2*3+2];

        float e1x = cx-bx, e1y = cy-by, e1z = cz-bz;
        float inv = 1.f / sqrtf(e1x*e1x + e1y*e1y + e1z*e1z + 1e-12f);
        e1x *= inv; e1y *= inv; e1z *= inv;
        float ux = bx-ax, uy = by-ay, uz = bz-az;
        float nx = uy*e1z - uz*e1y;
        float ny = uz*e1x - ux*e1z;
        float nz = ux*e1y - uy*e1x;
        inv = 1.f / sqrtf(nx*nx + ny*ny + nz*nz + 1e-12f);
        nx *= inv; ny *= inv; nz *= inv;
        float e2x = ny*e1z - nz*e1y;
        float e2y = nz*e1x - nx*e1z;
        float e2z = nx*e1y - ny*e1x;

        int hyb = hybrid[bt*MA_ + kk];
        const float* tor = (hyb == 0) ? sp2t : (hyb == 1) ? sp3t : ringt;
        float ct = cosf(wang), st = sinf(wang);
        float k1 = -wdist*ct;
        float k2 =  wdist*st;
        float c0 = cosf(tor[0]), s0 = sinf(tor[0]);
        float c1 = cosf(tor[1]), s1 = sinf(tor[1]);
        w0x = cx + k1*e1x + k2*c0*e2x + k2*s0*nx;
        w0y = cy + k1*e1y + k2*c0*e2y + k2*s0*ny;
        w0z = cz + k1*e1z + k2*c0*e2z + k2*s0*nz;
        w1x = cx + k1*e1x + k2*c1*e2x + k2*s1*nx;
        w1y = cy + k1*e1y + k2*c1*e2y + k2*s1*ny;
        w1z = cz + k1*e1z + k2*c1*e2z + k2*s1*nz;
        if (!mask) { w0x=w0y=w0z=BIG; w1x=w1y=w1z=BIG; }
        a_i = ai;
    }

    int pd = pdist[(size_t)(bt*A_ + a_i)*A_ + lane];
    unsigned m = __ballot_sync(0xFFFFFFFFu, pd >= 4);

    if (lane == 0) {
        Site st;
        st.x = cb[a_i*3+0]; st.y = cb[a_i*3+1]; st.z = cb[a_i*3+2];
        float ri   = lkp[(bt*A_ + a_i)*4 + 0];
        float dgi  = lkp[(bt*A_ + a_i)*4 + 1];
        float lami = lkp[(bt*A_ + a_i)*4 + 2];
        float invl = 1.f / lami;
        st.ri = ri;
        st.inv_lami = invl;
        st.cdg = mask ? (C_LK_ * dgi * invl) : 0.f;
        st.w0x = w0x; st.w0y = w0y; st.w0z = w0z;
        st.w1x = w1x; st.w1y = w1y; st.w1z = w1z;
        st.b_i = b;
        st.pdmask = m;
        st.pad0 = 0; st.pad1 = 0;
        g_sites[wgl] = st;
    }
}

// ---------------------------------------------------------------------------
// Phase A: coherent distance filter, warp-aggregated pair append.
// ---------------------------------------------------------------------------
__global__ void __launch_bounds__(256) filter_kernel(const float* __restrict__ lkg)
{
    const int p   = blockIdx.y;
    const int s0  = blockIdx.x * G_;
    const int zb  = blockIdx.z * CHUNK_;
    const int tid = threadIdx.x;
    const int lane = tid & 31;
    const int seg = ((blockIdx.x + 96*blockIdx.y)*ZCH_ + blockIdx.z) & (SEG_-1);
    const int siteBase = p*NPOL_ + s0;

    __shared__ Site sh[G_];
    if (tid < G_*4) ((float4*)sh)[tid] = ((const float4*)&g_sites[siteBase])[tid];
    __syncthreads();

    const float cutoff = lkg[0];
    const float c2 = cutoff * cutoff;

    u64 sx2[4], sy2[4], sz2[4];
    #pragma unroll
    for (int h = 0; h < 4; h++) {
        sx2[h] = pk2(sh[2*h].x, sh[2*h+1].x);
        sy2[h] = pk2(sh[2*h].y, sh[2*h+1].y);
        sz2[h] = pk2(sh[2*h].z, sh[2*h+1].z);
    }

    const int base = p*N_ + zb;

    #pragma unroll
    for (int it = 0; it < CHUNK_/256; it++) {
        const int j = it*256 + tid;
        ulonglong2 axy = g_axy[base + j];
        u64        az  = g_az [base + j];
        float2     rv  = g_rv [base + j];

        float d2s[8];
        #pragma unroll
        for (int h = 0; h < 4; h++) {
            u64 dx = add2(sx2[h], axy.x);
            u64 dy = add2(sy2[h], axy.y);
            u64 dz = add2(sz2[h], az);
            u64 t  = mul2(dx, dx);
            t = fma2(dy, dy, t);
            t = fma2(dz, dz, t);
            upk2(d2s[2*h], d2s[2*h+1], t);
        }

        float mn = fminf(fminf(fminf(d2s[0], d2s[1]), fminf(d2s[2], d2s[3])),
                         fminf(fminf(d2s[4], d2s[5]), fminf(d2s[6], d2s[7])));
        bool lhit = (mn < c2) & (rv.y != 0.f);
        unsigned wm = __ballot_sync(0xFFFFFFFFu, lhit);
        if (wm == 0) continue;

        unsigned hits = 0;
        if (lhit) {
            #pragma unroll
            for (int g = 0; g < G_; g++)
                if (d2s[g] < c2) hits |= (1u << g);
        }
        int n = __popc(hits);
        int incl = n;
        #pragma unroll
        for (int d = 1; d < 32; d <<= 1) {
            int t = __shfl_up_sync(0xFFFFFFFFu, incl, d);
            if (lane >= d) incl += t;
        }
        unsigned bpos = 0;
        if (lane == 31 && incl > 0)
            bpos = atomicAdd(&g_cnt[seg*32], (unsigned)incl);
        bpos = __shfl_sync(0xFFFFFFFFu, bpos, 31);

        int o = (int)bpos + incl - n;
        const unsigned jj = (unsigned)(zb + j);
        unsigned h = hits;
        while (h) {
            int g = __ffs(h) - 1; h &= h - 1;
            if (o < SEGCAP_)
                g_buf[seg*SEGCAP_ + o] = ((unsigned)(siteBase + g) << 12) | jj;
            o++;
        }
    }
}

// ---------------------------------------------------------------------------
// Phase B: dense evaluation of compacted pairs.
// ---------------------------------------------------------------------------
__global__ void __launch_bounds__(256) eval_kernel(
    const int*   __restrict__ msep,
    const float* __restrict__ lkg,
    float*       __restrict__ out)
{
    const int tid = threadIdx.x;
    const float ramp2  = lkg[1];
    const float d2low  = lkg[2];
    const float inv_r2 = 1.f / ramp2;
    const float thr_s  = (d2low + ramp2) * inv_r2;

    float a0[P_] = {0.f, 0.f};
    float a1[P_] = {0.f, 0.f};

    for (int seg = 0; seg < SEG_; seg++) {
        unsigned cnt = g_cnt[seg*32];
        if (cnt > SEGCAP_) cnt = SEGCAP_;
        for (unsigned i = blockIdx.x*256u + tid; i < cnt; i += NB_B_*256u) {
            unsigned v = g_buf[seg*SEGCAP_ + i];
            int sg = (int)(v >> 12);
            int jj = (int)(v & 4095u);
            int p  = (sg >= NPOL_) ? 1 : 0;

            const float4* sp = (const float4*)&g_sites[sg];
            float4 f0 = sp[0], f1 = sp[1], f2 = sp[2];
            int    b_i    = ((const int*)&sp[3])[0];
            unsigned pdm  = ((const unsigned*)&sp[3])[1];

            int bj = jj >> 5, aj = jj & 31;
            bool ok = (b_i == bj) ? (((pdm >> aj) & 1u) != 0u)
                                  : (msep[(p*B_ + b_i)*B_ + bj] >= 4);
            if (!ok) continue;

            float4 a  = g_apos[p*N_ + jj];   // x,y,z,rj
            float2 rv = g_rv [p*N_ + jj];    // rj, volj

            float dx = f0.x - a.x, dy = f0.y - a.y, dz = f0.z - a.z;
            float d2 = fmaxf(dx*dx + dy*dy + dz*dz, 0.01f);
            float d  = sqrtf(d2);
            float xx = (d - (f0.w + a.w)) * f1.y;     // inv_lami = f1.y
            float lk = f1.x * rv.y * __expf(-xx*xx) * __frcp_rn(d2);  // cdg = f1.x

            float ex = f1.z - a.x, ey = f1.w - a.y, ez = f2.x - a.z;  // w0
            float dw0 = ex*ex + ey*ey + ez*ez;
            ex = f2.y - a.x; ey = f2.z - a.y; ez = f2.w - a.z;        // w1
            float dw1 = ex*ex + ey*ey + ez*ez;
            float dwmin = fminf(dw0, dw1);

            float wt = __saturatef(fmaf(dwmin, -inv_r2, thr_s));
            float frac = wt*wt*(3.f - 2.f*wt);

            a0[p] += lk;
            a1[p] = fmaf(lk, frac, a1[p]);
        }
    }

    #pragma unroll
    for (int off = 16; off > 0; off >>= 1) {
        a0[0] += __shfl_xor_sync(0xFFFFFFFFu, a0[0], off);
        a0[1] += __shfl_xor_sync(0xFFFFFFFFu, a0[1], off);
        a1[0] += __shfl_xor_sync(0xFFFFFFFFu, a1[0], off);
        a1[1] += __shfl_xor_sync(0xFFFFFFFFu, a1[1], off);
    }
    __shared__ float red[4][8];
    int warp = tid >> 5, lane = tid & 31;
    if (lane == 0) {
        red[0][warp] = a0[0]; red[1][warp] = a0[1];
        red[2][warp] = a1[0]; red[3][warp] = a1[1];
    }
    __syncthreads();
    if (tid == 0) {
        float t0=0.f, t1=0.f, t2=0.f, t3=0.f;
        #pragma unroll
        for (int w = 0; w < 8; w++) {
            t0 += red[0][w]; t1 += red[1][w];
            t2 += red[2][w]; t3 += red[3][w];
        }
        if (t0 != 0.f || t2 != 0.f) { atomicAdd(&g_acc[0], (double)t0); atomicAdd(&g_acc[2], (double)t2); }
        if (t1 != 0.f || t3 != 0.f) { atomicAdd(&g_acc[1], (double)t1); atomicAdd(&g_acc[3], (double)t3); }
        __threadfence();
        int done = atomicAdd(&g_done, 1);
        if (done == NB_B_ - 1) {
            #pragma unroll
            for (int i = 0; i < 4; i++)
                out[i] = (float)atomicAdd(&g_acc[i], 0.0);
        }
    }
}

extern "C" void kernel_launch(void* const* d_in, const int* in_sizes, int n_in,
                              void* d_out, int out_size) {
    const float* coords       = (const float*)d_in[0];
    const int*   block_type   = (const int*)  d_in[1];
    const int*   msep         = (const int*)  d_in[2];
    const int*   bonds        = (const int*)  d_in[4];
    const int*   ranges       = (const int*)  d_in[5];
    const int*   n_donH       = (const int*)  d_in[6];
    const int*   n_acc        = (const int*)  d_in[7];
    const int*   donH_inds    = (const int*)  d_in[8];
    const int*   don_hvy_inds = (const int*)  d_in[9];
    const int*   acc_inds     = (const int*)  d_in[10];
    const int*   hybrid       = (const int*)  d_in[11];
    const int*   is_h         = (const int*)  d_in[12];
    const float* lkp          = (const float*)d_in[13];
    const int*   pdist        = (const int*)  d_in[14];
    const float* lkg          = (const float*)d_in[15];
    const float* wg           = (const float*)d_in[16];
    const float* sp2t         = (const float*)d_in[17];
    const float* sp3t         = (const float*)d_in[18];
    const float* ringt        = (const float*)d_in[19];

    prep_kernel<<<ATOM_BLKS_ + (P_*NPOL_)/8, 256>>>(
        coords, block_type, bonds, ranges, n_donH, n_acc,
        donH_inds, don_hvy_inds, acc_inds, hybrid, is_h,
        lkp, pdist, wg, sp2t, sp3t, ringt);

    dim3 gridA(NPOL_ / G_, P_, ZCH_);
    filter_kernel<<<gridA, 256>>>(lkg);

    eval_kernel<<<NB_B_, 256>>>(msep, lkg, (float*)d_out);
}

// round 4
// speedup vs baseline: 2.6530x; 1.7337x over previous
#include <cuda_runtime.h>
#include <cuda_bf16.h>

#define P_     2
#define B_     96
#define A_     32
#define N_     (B_*A_)        // 3072
#define MD_    4
#define MA_    4
#define NPOLB_ 8
#define NPOL_  (B_*NPOLB_)    // 768
#define G_     8              // sites per block == NPOLB_
#define ZCH_   4
#define CHUNK_ (N_/ZCH_)      // 768
#define QS_    512            // per-warp ring queue entries
#define C_LK_  0.0897935610625833f

typedef unsigned long long u64;

__device__ __forceinline__ u64 pk2(float lo, float hi) {
    u64 r; asm("mov.b64 %0,{%1,%2};" : "=l"(r) : "f"(lo), "f"(hi)); return r;
}
__device__ __forceinline__ void upk2(float& lo, float& hi, u64 v) {
    asm("mov.b64 {%0,%1},%2;" : "=f"(lo), "=f"(hi) : "l"(v));
}
__device__ __forceinline__ u64 add2(u64 a, u64 b) {
    u64 r; asm("add.rn.f32x2 %0,%1,%2;" : "=l"(r) : "l"(a), "l"(b)); return r;
}
__device__ __forceinline__ u64 mul2(u64 a, u64 b) {
    u64 r; asm("mul.rn.f32x2 %0,%1,%2;" : "=l"(r) : "l"(a), "l"(b)); return r;
}
__device__ __forceinline__ u64 fma2(u64 a, u64 b, u64 c) {
    u64 r; asm("fma.rn.f32x2 %0,%1,%2,%3;" : "=l"(r) : "l"(a), "l"(b), "l"(c)); return r;
}

struct __align__(16) Site {
    float x, y, z, ri;
    float cdg, inv_lami;
    float w0x, w0y;
    float w0z, w1x, w1y, w1z;
    int   b_i;
    unsigned pdmask;
    int   pad0, pad1;
};                              // 64 bytes

__device__ ulonglong2 g_axy[P_*N_];   // {(-x,-x),(-y,-y)}
__device__ ulonglong2 g_azw[P_*N_];   // { (-z,-z), bits(rj,volj) }
__device__ float4     g_apos[P_*N_];  // x,y,z,rj
__device__ double     g_acc[4];
__device__ int        g_done;

// ---------------------------------------------------------------------------
// Kernel 1: atom packing + accumulator init. Wide and shallow.
// ---------------------------------------------------------------------------
__global__ void __launch_bounds__(256) atom_prep_kernel(
    const float* __restrict__ coords,
    const int*   __restrict__ block_type,
    const int*   __restrict__ is_h,
    const float* __restrict__ lkp)
{
    int t = blockIdx.x * 256 + threadIdx.x;
    if (t < 4) g_acc[t] = 0.0;
    if (t == 4) g_done = 0;
    int p  = t / N_;
    int j  = t - p*N_;
    int bj = j >> 5;
    int aj = j & 31;
    int bt = block_type[p*B_ + bj];
    const float* c = coords + (size_t)t*3;
    float x = c[0], y = c[1], z = c[2];
    float rj   = lkp[(bt*A_ + aj)*4 + 0];
    float volj = lkp[(bt*A_ + aj)*4 + 3];
    if (is_h[bt*A_ + aj] != 0) volj = 0.f;
    ulonglong2 axy; axy.x = pk2(-x, -x); axy.y = pk2(-y, -y);
    g_axy[t] = axy;
    ulonglong2 azw; azw.x = pk2(-z, -z); azw.y = pk2(rj, volj);
    g_azw[t] = azw;
    g_apos[t] = make_float4(x, y, z, rj);
}

// ---------------------------------------------------------------------------
// Kernel 2: fused sites + filter + inline eval via per-warp smem queue.
// grid (B_, P_, ZCH_), 256 threads. Block bx owns the 8 sites of block bx.
// ---------------------------------------------------------------------------
__global__ void __launch_bounds__(256) fused_kernel(
    const float* __restrict__ coords,
    const int*   __restrict__ block_type,
    const int*   __restrict__ msep,
    const int*   __restrict__ bonds,
    const int*   __restrict__ ranges,
    const int*   __restrict__ n_donH,
    const int*   __restrict__ n_acc,
    const int*   __restrict__ donH_inds,
    const int*   __restrict__ don_hvy_inds,
    const int*   __restrict__ acc_inds,
    const int*   __restrict__ hybrid,
    const float* __restrict__ lkp,
    const int*   __restrict__ pdist,
    const float* __restrict__ lkg,
    const float* __restrict__ wg,
    const float* __restrict__ sp2t,
    const float* __restrict__ sp3t,
    const float* __restrict__ ringt,
    float*       __restrict__ out)
{
    const int p    = blockIdx.y;
    const int b    = blockIdx.x;           // residue block == site group
    const int zb   = blockIdx.z * CHUNK_;
    const int tid  = threadIdx.x;
    const int w    = tid >> 5;
    const int lane = tid & 31;

    __shared__ Site     sh[G_];
    __shared__ unsigned q[8][QS_];

    // ---- each warp computes one site (k = w) ----
    {
        const int k  = w;
        const int bt = block_type[p*B_ + b];
        const float* cb = coords + (size_t)((p*B_ + b)*A_) * 3;
        const float wdist = wg[0], wang = wg[1];
        const float BIG = 1.0e4f;

        int a_i;
        bool mask;
        float w0x=0.f, w0y=0.f, w0z=0.f, w1x=0.f, w1y=0.f, w1z=0.f;

        if (k < MD_) {
            mask = (k < n_donH[bt]);
            int hvy_i = don_hvy_inds[bt*MD_ + k];
            int H_i   = donH_inds[bt*MD_ + k];
            float hx = cb[hvy_i*3+0], hy = cb[hvy_i*3+1], hz = cb[hvy_i*3+2];
            float vx = cb[H_i*3+0]-hx, vy = cb[H_i*3+1]-hy, vz = cb[H_i*3+2]-hz;
            float inv = 1.f / sqrtf(vx*vx + vy*vy + vz*vz + 1e-12f);
            w0x = hx + wdist*vx*inv;
            w0y = hy + wdist*vy*inv;
            w0z = hz + wdist*vz*inv;
            w1x = w1y = w1z = BIG;
            if (!mask) { w0x = w0y = w0z = BIG; }
            a_i = hvy_i;
        } else {
            int kk = k - MD_;
            mask = (kk < n_acc[bt]);
            int ai    = acc_inds[bt*MA_ + kk];
            int r1    = ranges[(bt*A_ + ai)*2 + 0];
            int base  = bonds [(bt*A_ + r1)*2 + 1];
            int r2    = ranges[(bt*A_ + base)*2 + 0];
            int base2 = bonds [(bt*A_ + r2)*2 + 1];

            float cx = cb[ai*3+0],    cy = cb[ai*3+1],    cz = cb[ai*3+2];
            float bx = cb[base*3+0],  by = cb[base*3+1],  bz = cb[base*3+2];
            float ax = cb[base2*3+0], ay = cb[base2*3+1], az = cb[base2*3+2];

            float e1x = cx-bx, e1y = cy-by, e1z = cz-bz;
            float inv = 1.f / sqrtf(e1x*e1x + e1y*e1y + e1z*e1z + 1e-12f);
            e1x *= inv; e1y *= inv; e1z *= inv;
            float ux = bx-ax, uy = by-ay, uz = bz-az;
            float nx = uy*e1z - uz*e1y;
            float ny = uz*e1x - ux*e1z;
            float nz = ux*e1y - uy*e1x;
            inv = 1.f / sqrtf(nx*nx + ny*ny + nz*nz + 1e-12f);
            nx *= inv; ny *= inv; nz *= inv;
            float e2x = ny*e1z - nz*e1y;
            float e2y = nz*e1x - nx*e1z;
            float e2z = nx*e1y - ny*e1x;

            int hyb = hybrid[bt*MA_ + kk];
            const float* tor = (hyb == 0) ? sp2t : (hyb == 1) ? sp3t : ringt;
            float ct = cosf(wang), st = sinf(wang);
            float k1 = -wdist*ct;
            float k2 =  wdist*st;
            float c0 = cosf(tor[0]), s0 = sinf(tor[0]);
            float c1 = cosf(tor[1]), s1 = sinf(tor[1]);
            w0x = cx + k1*e1x + k2*c0*e2x + k2*s0*nx;
            w0y = cy + k1*e1y + k2*c0*e2y + k2*s0*ny;
            w0z = cz + k1*e1z + k2*c0*e2z + k2*s0*nz;
            w1x = cx + k1*e1x + k2*c1*e2x + k2*s1*nx;
            w1y = cy + k1*e1y + k2*c1*e2y + k2*s1*ny;
            w1z = cz + k1*e1z + k2*c1*e2z + k2*s1*nz;
            if (!mask) { w0x=w0y=w0z=BIG; w1x=w1y=w1z=BIG; }
            a_i = ai;
        }

        int pd = pdist[(size_t)(bt*A_ + a_i)*A_ + lane];
        unsigned m = __ballot_sync(0xFFFFFFFFu, pd >= 4);

        if (lane == 0) {
            Site st;
            st.x = cb[a_i*3+0]; st.y = cb[a_i*3+1]; st.z = cb[a_i*3+2];
            float ri   = lkp[(bt*A_ + a_i)*4 + 0];
            float dgi  = lkp[(bt*A_ + a_i)*4 + 1];
            float lami = lkp[(bt*A_ + a_i)*4 + 2];
            float invl = 1.f / lami;
            st.ri = ri;
            st.inv_lami = invl;
            st.cdg = mask ? (C_LK_ * dgi * invl) : 0.f;
            st.w0x = w0x; st.w0y = w0y; st.w0z = w0z;
            st.w1x = w1x; st.w1y = w1y; st.w1z = w1z;
            st.b_i = b;
            st.pdmask = m;
            st.pad0 = 0; st.pad1 = 0;
            sh[k] = st;
        }
    }
    __syncthreads();

    const float cutoff = lkg[0];
    const float ramp2  = lkg[1];
    const float d2low  = lkg[2];
    const float c2     = cutoff * cutoff;
    const float inv_r2 = 1.f / ramp2;
    const float thr_s  = (d2low + ramp2) * inv_r2;

    u64 sx2[4], sy2[4], sz2[4];
    #pragma unroll
    for (int h = 0; h < 4; h++) {
        sx2[h] = pk2(sh[2*h].x, sh[2*h+1].x);
        sy2[h] = pk2(sh[2*h].y, sh[2*h+1].y);
        sz2[h] = pk2(sh[2*h].z, sh[2*h+1].z);
    }

    float a0 = 0.f, a1 = 0.f;
    int qn = 0, qd = 0;
    const int base = p*N_ + zb;

    // evaluator for one queued pair (v = g<<12 | j)
    auto evalPair = [&](unsigned v) {
        int g  = (int)(v >> 12);
        int jj = (int)(v & 4095u);
        const Site& s = sh[g];
        int bj = jj >> 5, aj = jj & 31;
        bool ok = (s.b_i == bj) ? (((s.pdmask >> aj) & 1u) != 0u)
                                : (msep[(p*B_ + s.b_i)*B_ + bj] >= 4);
        if (!ok) return;
        float4 a = g_apos[p*N_ + jj];          // x,y,z,rj
        float rjv, volj;
        upk2(rjv, volj, g_azw[p*N_ + jj].y);

        float dx = s.x - a.x, dy = s.y - a.y, dz = s.z - a.z;
        float d2 = fmaxf(dx*dx + dy*dy + dz*dz, 0.01f);
        float d  = sqrtf(d2);
        float xx = (d - (s.ri + a.w)) * s.inv_lami;
        float lk = s.cdg * volj * __expf(-xx*xx) * __frcp_rn(d2);

        float ex = s.w0x - a.x, ey = s.w0y - a.y, ez = s.w0z - a.z;
        float dw0 = ex*ex + ey*ey + ez*ez;
        ex = s.w1x - a.x; ey = s.w1y - a.y; ez = s.w1z - a.z;
        float dw1 = ex*ex + ey*ey + ez*ez;
        float dwmin = fminf(dw0, dw1);

        float wt = __saturatef(fmaf(dwmin, -inv_r2, thr_s));
        float frac = wt*wt*(3.f - 2.f*wt);

        a0 += lk;
        a1 = fmaf(lk, frac, a1);
    };

    #pragma unroll
    for (int it = 0; it < CHUNK_/256; it++) {
        const int j = it*256 + tid;
        ulonglong2 axy = g_axy[base + j];
        ulonglong2 azw = g_azw[base + j];

        float d2s[8];
        #pragma unroll
        for (int h = 0; h < 4; h++) {
            u64 dx = add2(sx2[h], axy.x);
            u64 dy = add2(sy2[h], axy.y);
            u64 dz = add2(sz2[h], azw.x);
            u64 t  = mul2(dx, dx);
            t = fma2(dy, dy, t);
            t = fma2(dz, dz, t);
            upk2(d2s[2*h], d2s[2*h+1], t);
        }

        float rjv, volj;
        upk2(rjv, volj, azw.y);
        float mn = fminf(fminf(fminf(d2s[0], d2s[1]), fminf(d2s[2], d2s[3])),
                         fminf(fminf(d2s[4], d2s[5]), fminf(d2s[6], d2s[7])));
        bool lhit = (mn < c2) & (volj != 0.f);
        unsigned wm = __ballot_sync(0xFFFFFFFFu, lhit);
        if (wm == 0) continue;

        unsigned hits = 0;
        if (lhit) {
            #pragma unroll
            for (int g = 0; g < G_; g++)
                if (d2s[g] < c2) hits |= (1u << g);
        }
        int n = __popc(hits);
        int incl = n;
        #pragma unroll
        for (int d = 1; d < 32; d <<= 1) {
            int t = __shfl_up_sync(0xFFFFFFFFu, incl, d);
            if (lane >= d) incl += t;
        }
        int total = __shfl_sync(0xFFFFFFFFu, incl, 31);

        int pos = qn + incl - n;
        const unsigned jj = (unsigned)(zb + j);
        unsigned h = hits;
        while (h) {
            int g = __ffs(h) - 1; h &= h - 1;
            q[w][pos & (QS_-1)] = ((unsigned)g << 12) | jj;
            pos++;
        }
        qn += total;
        __syncwarp();

        while (qn - qd >= 32) {
            unsigned v = q[w][(qd + lane) & (QS_-1)];
            evalPair(v);
            qd += 32;
        }
    }

    // drain remainder
    {
        int rem = qn - qd;
        if (lane < rem) {
            unsigned v = q[w][(qd + lane) & (QS_-1)];
            evalPair(v);
        }
    }

    // reduction
    #pragma unroll
    for (int off = 16; off > 0; off >>= 1) {
        a0 += __shfl_xor_sync(0xFFFFFFFFu, a0, off);
        a1 += __shfl_xor_sync(0xFFFFFFFFu, a1, off);
    }
    __shared__ float red0[8], red1[8];
    if (lane == 0) { red0[w] = a0; red1[w] = a1; }
    __syncthreads();
    if (tid == 0) {
        float t0 = 0.f, t1 = 0.f;
        #pragma unroll
        for (int i = 0; i < 8; i++) { t0 += red0[i]; t1 += red1[i]; }
        atomicAdd(&g_acc[0 + p], (double)t0);
        atomicAdd(&g_acc[2 + p], (double)t1);
        __threadfence();
        int done = atomicAdd(&g_done, 1);
        if (done == B_*P_*ZCH_ - 1) {
            #pragma unroll
            for (int i = 0; i < 4; i++)
                out[i] = (float)atomicAdd(&g_acc[i], 0.0);
        }
    }
}

extern "C" void kernel_launch(void* const* d_in, const int* in_sizes, int n_in,
                              void* d_out, int out_size) {
    const float* coords       = (const float*)d_in[0];
    const int*   block_type   = (const int*)  d_in[1];
    const int*   msep         = (const int*)  d_in[2];
    const int*   bonds        = (const int*)  d_in[4];
    const int*   ranges       = (const int*)  d_in[5];
    const int*   n_donH       = (const int*)  d_in[6];
    const int*   n_acc        = (const int*)  d_in[7];
    const int*   donH_inds    = (const int*)  d_in[8];
    const int*   don_hvy_inds = (const int*)  d_in[9];
    const int*   acc_inds     = (const int*)  d_in[10];
    const int*   hybrid       = (const int*)  d_in[11];
    const int*   is_h         = (const int*)  d_in[12];
    const float* lkp          = (const float*)d_in[13];
    const int*   pdist        = (const int*)  d_in[14];
    const float* lkg          = (const float*)d_in[15];
    const float* wg           = (const float*)d_in[16];
    const float* sp2t         = (const float*)d_in[17];
    const float* sp3t         = (const float*)d_in[18];
    const float* ringt        = (const float*)d_in[19];

    atom_prep_kernel<<<(P_*N_)/256, 256>>>(coords, block_type, is_h, lkp);

    dim3 grid(B_, P_, ZCH_);
    fused_kernel<<<grid, 256>>>(
        coords, block_type, msep, bonds, ranges, n_donH, n_acc,
        donH_inds, don_hvy_inds, acc_inds, hybrid,
        lkp, pdist, lkg, wg, sp2t, sp3t, ringt, (float*)d_out);
}

// round 5
// speedup vs baseline: 3.5473x; 1.3371x over previous
#include <cuda_runtime.h>
#include <cuda_bf16.h>

#define P_     2
#define B_     96
#define A_     32
#define N_     (B_*A_)        // 3072
#define MD_    4
#define MA_    4
#define NPOLB_ 8
#define NPOL_  (B_*NPOLB_)    // 768
#define G_     8
#define ZCH_   2
#define CHUNK_ (N_/ZCH_)      // 1536 -> 6 iters of 256
#define QS_    256
#define NT_    24
#define C_LK_  0.0897935610625833f

typedef unsigned long long u64;

__device__ __forceinline__ u64 pk2(float lo, float hi) {
    u64 r; asm("mov.b64 %0,{%1,%2};" : "=l"(r) : "f"(lo), "f"(hi)); return r;
}
__device__ __forceinline__ void upk2(float& lo, float& hi, u64 v) {
    asm("mov.b64 {%0,%1},%2;" : "=f"(lo), "=f"(hi) : "l"(v));
}
__device__ __forceinline__ u64 add2(u64 a, u64 b) {
    u64 r; asm("add.rn.f32x2 %0,%1,%2;" : "=l"(r) : "l"(a), "l"(b)); return r;
}
__device__ __forceinline__ u64 mul2(u64 a, u64 b) {
    u64 r; asm("mul.rn.f32x2 %0,%1,%2;" : "=l"(r) : "l"(a), "l"(b)); return r;
}
__device__ __forceinline__ u64 fma2(u64 a, u64 b, u64 c) {
    u64 r; asm("fma.rn.f32x2 %0,%1,%2,%3;" : "=l"(r) : "l"(a), "l"(b), "l"(c)); return r;
}

struct __align__(16) Site {       // per-(pose,block,k), built in fused smem
    float x, y, z, ri;
    float cdg, inv_lami;
    float w0x, w0y;
    float w0z, w1x, w1y, w1z;
    int   b_i;
    unsigned pdmask;
    int   pad0, pad1;
};                                // 64B

struct __align__(16) SiteT {      // pose-independent, per-(block_type,k)
    int   a_i, o1, o2, pad;
    float k1, p0c, p0s, ri;       // donor: k1 = wdist
    float p1c, p1s, cdg, inv_lami;
    unsigned pdmask; int pad1, pad2, pad3;
};                                // 64B

__device__ ulonglong2 g_axy[P_*N_];    // {(-x,-x),(-y,-y)}  (hydrogens poisoned)
__device__ u64        g_az [P_*N_];    // (-z,-z)
__device__ float4     g_apos[P_*N_];   // x,y,z,rj (real coords)
__device__ float2     g_rjvol[P_*N_];  // rj, volj (0 if hydrogen)
__device__ SiteT      g_stab[NT_*G_];
__device__ double     g_acc[4];
__device__ int        g_done;

// ---------------------------------------------------------------------------
// Prep: blocks [0,24): atoms.  blocks [24,48): site-table (warp per entry).
// ---------------------------------------------------------------------------
__global__ void __launch_bounds__(256) prep_kernel(
    const float* __restrict__ coords,
    const int*   __restrict__ block_type,
    const int*   __restrict__ bonds,
    const int*   __restrict__ ranges,
    const int*   __restrict__ n_donH,
    const int*   __restrict__ n_acc,
    const int*   __restrict__ donH_inds,
    const int*   __restrict__ don_hvy_inds,
    const int*   __restrict__ acc_inds,
    const int*   __restrict__ hybrid,
    const int*   __restrict__ is_h,
    const float* __restrict__ lkp,
    const int*   __restrict__ pdist,
    const float* __restrict__ wg,
    const float* __restrict__ sp2t,
    const float* __restrict__ sp3t,
    const float* __restrict__ ringt)
{
    if (blockIdx.x < 24) {
        int t = blockIdx.x * 256 + threadIdx.x;
        if (t < 4) g_acc[t] = 0.0;
        if (t == 4) g_done = 0;
        int p  = t / N_;
        int j  = t - p*N_;
        int bj = j >> 5;
        int aj = j & 31;
        int bt = block_type[p*B_ + bj];
        const float* c = coords + (size_t)t*3;
        float x = c[0], y = c[1], z = c[2];
        float rj   = lkp[(bt*A_ + aj)*4 + 0];
        float volj = lkp[(bt*A_ + aj)*4 + 3];
        bool hyd = (is_h[bt*A_ + aj] != 0);
        float px = hyd ? 1.0e5f : -x;
        float py = hyd ? 1.0e5f : -y;
        float pz = hyd ? 1.0e5f : -z;
        ulonglong2 axy; axy.x = pk2(px, px); axy.y = pk2(py, py);
        g_axy[t] = axy;
        g_az[t]  = pk2(pz, pz);
        g_apos[t]  = make_float4(x, y, z, rj);
        g_rjvol[t] = make_float2(rj, hyd ? 0.f : volj);
        return;
    }

    int idx  = (blockIdx.x - 24) * 8 + (threadIdx.x >> 5);   // [0,192)
    int lane = threadIdx.x & 31;
    if (idx >= NT_*G_) return;
    int bt = idx >> 3;
    int k  = idx & 7;

    float wdist = wg[0], wang = wg[1];
    int a_i, o1 = 0, o2 = 0;
    float k1 = 0.f, p0c = 0.f, p0s = 0.f, p1c = 0.f, p1s = 0.f;
    bool mask;

    if (k < MD_) {
        mask = (k < n_donH[bt]);
        a_i = don_hvy_inds[bt*MD_ + k];
        o1  = donH_inds[bt*MD_ + k];
        k1  = wdist;
    } else {
        int kk = k - MD_;
        mask = (kk < n_acc[bt]);
        a_i = acc_inds[bt*MA_ + kk];
        int r1 = ranges[(bt*A_ + a_i)*2 + 0];
        o1     = bonds [(bt*A_ + r1)*2 + 1];
        int r2 = ranges[(bt*A_ + o1)*2 + 0];
        o2     = bonds [(bt*A_ + r2)*2 + 1];
        int hyb = hybrid[bt*MA_ + kk];
        const float* tor = (hyb == 0) ? sp2t : (hyb == 1) ? sp3t : ringt;
        float ct = cosf(wang), st = sinf(wang);
        k1 = -wdist*ct;
        float k2 = wdist*st;
        p0c = k2*cosf(tor[0]); p0s = k2*sinf(tor[0]);
        p1c = k2*cosf(tor[1]); p1s = k2*sinf(tor[1]);
    }

    int pd = pdist[(size_t)(bt*A_ + a_i)*A_ + lane];
    unsigned m = __ballot_sync(0xFFFFFFFFu, pd >= 4);

    if (lane == 0) {
        SiteT t;
        t.a_i = a_i; t.o1 = o1; t.o2 = o2; t.pad = 0;
        float ri   = lkp[(bt*A_ + a_i)*4 + 0];
        float dgi  = lkp[(bt*A_ + a_i)*4 + 1];
        float lami = lkp[(bt*A_ + a_i)*4 + 2];
        float invl = 1.f / lami;
        t.k1 = k1; t.p0c = p0c; t.p0s = p0s; t.ri = ri;
        t.p1c = p1c; t.p1s = p1s;
        t.cdg = mask ? (C_LK_ * dgi * invl) : 0.f;
        t.inv_lami = invl;
        t.pdmask = m; t.pad1 = t.pad2 = t.pad3 = 0;
        g_stab[idx] = t;
    }
}

// ---------------------------------------------------------------------------
// Fused: site build (3-level chain) + packed filter + queued coherent eval.
// grid (B_, P_, ZCH_), 256 threads.
// ---------------------------------------------------------------------------
__global__ void __launch_bounds__(256) fused_kernel(
    const float* __restrict__ coords,
    const int*   __restrict__ block_type,
    const int*   __restrict__ msep,
    const float* __restrict__ lkg,
    float*       __restrict__ out)
{
    const int p    = blockIdx.y;
    const int b    = blockIdx.x;
    const int zb   = blockIdx.z * CHUNK_;
    const int tid  = threadIdx.x;
    const int w    = tid >> 5;
    const int lane = tid & 31;

    __shared__ Site     sh[G_];
    __shared__ unsigned q[G_][QS_];

    // ---- site build: warp w builds site k=w from the precomputed table ----
    {
        const int bt = block_type[p*B_ + b];
        SiteT t = g_stab[bt*G_ + w];
        const float* cb = coords + (size_t)((p*B_ + b)*A_) * 3;
        const float BIG = 1.0e4f;

        float px = cb[t.a_i*3+0], py = cb[t.a_i*3+1], pz = cb[t.a_i*3+2];
        float w0x, w0y, w0z, w1x, w1y, w1z;

        if (w < MD_) {
            float vx = cb[t.o1*3+0]-px, vy = cb[t.o1*3+1]-py, vz = cb[t.o1*3+2]-pz;
            float inv = rsqrtf(vx*vx + vy*vy + vz*vz + 1e-12f);
            float s = t.k1 * inv;     // k1 = wdist
            w0x = px + s*vx; w0y = py + s*vy; w0z = pz + s*vz;
            w1x = w1y = w1z = BIG;
        } else {
            float bx = cb[t.o1*3+0], by = cb[t.o1*3+1], bz = cb[t.o1*3+2];
            float ax = cb[t.o2*3+0], ay = cb[t.o2*3+1], az = cb[t.o2*3+2];
            float e1x = px-bx, e1y = py-by, e1z = pz-bz;
            float inv = rsqrtf(e1x*e1x + e1y*e1y + e1z*e1z + 1e-12f);
            e1x *= inv; e1y *= inv; e1z *= inv;
            float ux = bx-ax, uy = by-ay, uz = bz-az;
            float nx = uy*e1z - uz*e1y;
            float ny = uz*e1x - ux*e1z;
            float nz = ux*e1y - uy*e1x;
            inv = rsqrtf(nx*nx + ny*ny + nz*nz + 1e-12f);
            nx *= inv; ny *= inv; nz *= inv;
            float e2x = ny*e1z - nz*e1y;
            float e2y = nz*e1x - nx*e1z;
            float e2z = nx*e1y - ny*e1x;
            w0x = px + t.k1*e1x + t.p0c*e2x + t.p0s*nx;
            w0y = py + t.k1*e1y + t.p0c*e2y + t.p0s*ny;
            w0z = pz + t.k1*e1z + t.p0c*e2z + t.p0s*nz;
            w1x = px + t.k1*e1x + t.p1c*e2x + t.p1s*nx;
            w1y = py + t.k1*e1y + t.p1c*e2y + t.p1s*ny;
            w1z = pz + t.k1*e1z + t.p1c*e2z + t.p1s*nz;
        }

        if (lane == 0) {
            Site s;
            s.x = px; s.y = py; s.z = pz; s.ri = t.ri;
            s.cdg = t.cdg; s.inv_lami = t.inv_lami;
            s.w0x = w0x; s.w0y = w0y; s.w0z = w0z;
            s.w1x = w1x; s.w1y = w1y; s.w1z = w1z;
            s.b_i = b; s.pdmask = t.pdmask;
            s.pad0 = 0; s.pad1 = 0;
            sh[w] = s;
        }
    }
    __syncthreads();

    const float cutoff = lkg[0];
    const float ramp2  = lkg[1];
    const float d2low  = lkg[2];
    const float c2     = cutoff * cutoff;
    const float inv_r2 = 1.f / ramp2;
    const float thr_s  = (d2low + ramp2) * inv_r2;

    u64 sx2[4], sy2[4], sz2[4];
    #pragma unroll
    for (int h = 0; h < 4; h++) {
        sx2[h] = pk2(sh[2*h].x, sh[2*h+1].x);
        sy2[h] = pk2(sh[2*h].y, sh[2*h+1].y);
        sz2[h] = pk2(sh[2*h].z, sh[2*h+1].z);
    }

    float a0 = 0.f, a1 = 0.f;
    int qn = 0, qd = 0;
    const int base = p*N_ + zb;
    const unsigned lt = (1u << lane) - 1u;

    auto evalPair = [&](unsigned v) {
        int g  = (int)(v >> 12);
        int jj = (int)(v & 4095u);
        const Site& s = sh[g];
        int bj = jj >> 5, aj = jj & 31;
        bool ok = (s.b_i == bj) ? (((s.pdmask >> aj) & 1u) != 0u)
                                : (msep[(p*B_ + s.b_i)*B_ + bj] >= 4);
        if (!ok) return;
        float4 a  = g_apos[p*N_ + jj];
        float2 rv = g_rjvol[p*N_ + jj];

        float dx = s.x - a.x, dy = s.y - a.y, dz = s.z - a.z;
        float d2 = fmaxf(dx*dx + dy*dy + dz*dz, 0.01f);
        float d  = sqrtf(d2);
        float xx = (d - (s.ri + rv.x)) * s.inv_lami;
        float lk = s.cdg * rv.y * __expf(-xx*xx) * __frcp_rn(d2);

        float ex = s.w0x - a.x, ey = s.w0y - a.y, ez = s.w0z - a.z;
        float dw0 = ex*ex + ey*ey + ez*ez;
        ex = s.w1x - a.x; ey = s.w1y - a.y; ez = s.w1z - a.z;
        float dw1 = ex*ex + ey*ey + ez*ez;
        float dwmin = fminf(dw0, dw1);

        float wt = __saturatef(fmaf(dwmin, -inv_r2, thr_s));
        float frac = wt*wt*(3.f - 2.f*wt);

        a0 += lk;
        a1 = fmaf(lk, frac, a1);
    };

    ulonglong2 axy = g_axy[base + tid];
    u64        az  = g_az [base + tid];

    #pragma unroll
    for (int it = 0; it < CHUNK_/256; it++) {
        ulonglong2 caxy = axy;
        u64        caz  = az;
        if (it + 1 < CHUNK_/256) {
            axy = g_axy[base + (it+1)*256 + tid];
            az  = g_az [base + (it+1)*256 + tid];
        }

        float d2s[8];
        #pragma unroll
        for (int h = 0; h < 4; h++) {
            u64 dx = add2(sx2[h], caxy.x);
            u64 dy = add2(sy2[h], caxy.y);
            u64 dz = add2(sz2[h], caz);
            u64 t  = mul2(dx, dx);
            t = fma2(dy, dy, t);
            t = fma2(dz, dz, t);
            upk2(d2s[2*h], d2s[2*h+1], t);
        }

        unsigned hits = 0;
        #pragma unroll
        for (int g = 0; g < G_; g++)
            if (d2s[g] < c2) hits |= (1u << g);
        int n = __popc(hits);

        unsigned b0 = __ballot_sync(0xFFFFFFFFu, n & 1);
        unsigned b1 = __ballot_sync(0xFFFFFFFFu, n & 2);
        unsigned b2 = __ballot_sync(0xFFFFFFFFu, n & 4);
        unsigned b3 = __ballot_sync(0xFFFFFFFFu, n & 8);
        int total = __popc(b0) + (__popc(b1) << 1) + (__popc(b2) << 2) + (__popc(b3) << 3);
        if (total == 0) continue;
        int excl = __popc(b0 & lt) + (__popc(b1 & lt) << 1)
                 + (__popc(b2 & lt) << 2) + (__popc(b3 & lt) << 3);

        int pos = qn + excl;
        const unsigned jj = (unsigned)(zb + it*256 + tid);
        unsigned h = hits;
        while (h) {
            int g = __ffs(h) - 1; h &= h - 1;
            q[w][pos & (QS_-1)] = ((unsigned)g << 12) | jj;
            pos++;
        }
        qn += total;

        if (qn - qd >= 32) {
            __syncwarp();
            do {
                unsigned v = q[w][(qd + lane) & (QS_-1)];
                evalPair(v);
                qd += 32;
            } while (qn - qd >= 32);
        }
    }

    {
        __syncwarp();
        int rem = qn - qd;
        if (lane < rem) {
            unsigned v = q[w][(qd + lane) & (QS_-1)];
            evalPair(v);
        }
    }

    #pragma unroll
    for (int off = 16; off > 0; off >>= 1) {
        a0 += __shfl_xor_sync(0xFFFFFFFFu, a0, off);
        a1 += __shfl_xor_sync(0xFFFFFFFFu, a1, off);
    }
    __shared__ float red0[8], red1[8];
    if (lane == 0) { red0[w] = a0; red1[w] = a1; }
    __syncthreads();
    if (tid == 0) {
        float t0 = 0.f, t1 = 0.f;
        #pragma unroll
        for (int i = 0; i < 8; i++) { t0 += red0[i]; t1 += red1[i]; }
        atomicAdd(&g_acc[0 + p], (double)t0);
        atomicAdd(&g_acc[2 + p], (double)t1);
        __threadfence();
        int done = atomicAdd(&g_done, 1);
        if (done == B_*P_*ZCH_ - 1) {
            #pragma unroll
            for (int i = 0; i < 4; i++)
                out[i] = (float)atomicAdd(&g_acc[i], 0.0);
        }
    }
}

extern "C" void kernel_launch(void* const* d_in, const int* in_sizes, int n_in,
                              void* d_out, int out_size) {
    const float* coords       = (const float*)d_in[0];
    const int*   block_type   = (const int*)  d_in[1];
    const int*   msep         = (const int*)  d_in[2];
    const int*   bonds        = (const int*)  d_in[4];
    const int*   ranges       = (const int*)  d_in[5];
    const int*   n_donH       = (const int*)  d_in[6];
    const int*   n_acc        = (const int*)  d_in[7];
    const int*   donH_inds    = (const int*)  d_in[8];
    const int*   don_hvy_inds = (const int*)  d_in[9];
    const int*   acc_inds     = (const int*)  d_in[10];
    const int*   hybrid       = (const int*)  d_in[11];
    const int*   is_h         = (const int*)  d_in[12];
    const float* lkp          = (const float*)d_in[13];
    const int*   pdist        = (const int*)  d_in[14];
    const float* lkg          = (const float*)d_in[15];
    const float* wg           = (const float*)d_in[16];
    const float* sp2t         = (const float*)d_in[17];
    const float* sp3t         = (const float*)d_in[18];
    const float* ringt        = (const float*)d_in[19];

    prep_kernel<<<48, 256>>>(
        coords, block_type, bonds, ranges, n_donH, n_acc,
        donH_inds, don_hvy_inds, acc_inds, hybrid, is_h,
        lkp, pdist, wg, sp2t, sp3t, ringt);

    dim3 grid(B_, P_, ZCH_);
    fused_kernel<<<grid, 256>>>(coords, block_type, msep, lkg, (float*)d_out);
}